// round 4
// baseline (speedup 1.0000x reference)
#include <cuda_runtime.h>

// HandGraphConvNet fused: 2-layer GCN + BN(eval) + relu + residual, fp32.
//   Y  = A @ X          (sparse A: <=6 nnz/row, fixed hand-skeleton pattern)
//   H  = relu(Y @ W1' + beta1')      (never materialized)
//   S2 = H @ W2'
//   out = A @ S2 + beta2' + x
// Warp <-> joint (21 warps), lane <-> sample, 2 samples/thread.
// Occupancy play: <=48 regs (launch_bounds 672,2) -> 2 blocks/SM. Adjacency
// values live in shared (re-read per phase), offsets in __constant__, so the
// channel loop's live set is just the 16 accumulator regs + transients.

#define NJ 21
#define HDIM 42
#define HIDDEN 64
#define SPT 2
#define SPB 64                // 32 lanes * 2
#define NTHREADS 672          // 21 warps
#define BN_EPS 1e-5f

typedef unsigned long long ull;

// fixed adjacency sparsity: flat neighbor ids (zero-padded) and counts
__constant__ int c_nbr[NJ * 6] = {
    0,1,5,9,13,17,
    0,1,2,0,0,0, 1,2,3,0,0,0, 2,3,4,0,0,0, 3,4,0,0,0,0,
    0,5,6,0,0,0, 5,6,7,0,0,0, 6,7,8,0,0,0, 7,8,0,0,0,0,
    0,9,10,0,0,0, 9,10,11,0,0,0, 10,11,12,0,0,0, 11,12,0,0,0,0,
    0,13,14,0,0,0, 13,14,15,0,0,0, 14,15,16,0,0,0, 15,16,0,0,0,0,
    0,17,18,0,0,0, 17,18,19,0,0,0, 18,19,20,0,0,0, 19,20,0,0,0,0};
__constant__ int c_cnt[NJ] = {6,3,3,3,2,3,3,3,2,3,3,3,2,3,3,3,2,3,3,3,2};

__device__ __forceinline__ ull pk2(float lo, float hi) {
    ull r; asm("mov.b64 %0, {%1, %2};" : "=l"(r) : "f"(lo), "f"(hi)); return r;
}
__device__ __forceinline__ void upk2(ull v, float& lo, float& hi) {
    asm("mov.b64 {%0, %1}, %2;" : "=f"(lo), "=f"(hi) : "l"(v));
}
__device__ __forceinline__ ull ffma2(ull a, ull b, ull c) {
    ull d; asm("fma.rn.f32x2 %0, %1, %2, %3;" : "=l"(d) : "l"(a), "l"(b), "l"(c)); return d;
}
__device__ __forceinline__ ull fadd2(ull a, ull b) {
    ull d; asm("add.rn.f32x2 %0, %1, %2;" : "=l"(d) : "l"(a), "l"(b)); return d;
}

__global__ __launch_bounds__(NTHREADS, 2)
void hand_gcn_kernel(const float* __restrict__ x,  const float* __restrict__ adj,
                     const float* __restrict__ W1, const float* __restrict__ b1,
                     const float* __restrict__ W2, const float* __restrict__ b2,
                     const float* __restrict__ g1, const float* __restrict__ be1,
                     const float* __restrict__ m1, const float* __restrict__ v1,
                     const float* __restrict__ g2, const float* __restrict__ be2,
                     const float* __restrict__ m2, const float* __restrict__ v2,
                     float* __restrict__ out, int nsamples)
{
    // lane word-stride 42 mod 32 = 10 -> 64-bit accesses conflict-free
    __shared__ alignas(16) float xs [SPB * HDIM];   // staged X (never overwritten)
    __shared__ alignas(16) float s2s[SPB * HDIM];   // S2 scratch
    __shared__ float4 cka[32];    // folded W1' column pair
    __shared__ float4 ckb[32];    // folded W2' row pair
    __shared__ float2 ckc[32];    // folded beta1' pair
    __shared__ ull    adjp[NJ * 6]; // packed (a,a) adjacency values
    __shared__ float2 beta2s;

    const int tid = threadIdx.x;
    const int j   = tid >> 5;         // joint (warp)
    const int sl  = tid & 31;         // lane / sample slot
    const long long base  = (long long)blockIdx.x * (SPB * HDIM);
    const long long total = (long long)nsamples * HDIM;

    // ---- stage X: 672 float4 = exactly 1 per thread ----
    const int N4 = SPB * HDIM / 4;
    float4* xs4 = (float4*)xs;
    {
        long long g = base + 4LL * tid;
        float4 v = make_float4(0.f, 0.f, 0.f, 0.f);
        if (g < total) v = *(const float4*)(x + g);
        xs4[tid] = v;
    }

    // ---- fold BN into weights/biases ----
    if (tid < 32) {
        int c0 = 2 * tid, c1 = c0 + 1;
        float al0 = g1[c0] * rsqrtf(v1[c0] + BN_EPS);
        float al1 = g1[c1] * rsqrtf(v1[c1] + BN_EPS);
        cka[tid] = make_float4(W1[c0] * al0, W1[c1] * al1,
                               W1[HIDDEN + c0] * al0, W1[HIDDEN + c1] * al1);
        ckc[tid] = make_float2((b1[c0] - m1[c0]) * al0 + be1[c0],
                               (b1[c1] - m1[c1]) * al1 + be1[c1]);
        float a20 = g2[0] * rsqrtf(v2[0] + BN_EPS);
        float a21 = g2[1] * rsqrtf(v2[1] + BN_EPS);
        ckb[tid] = make_float4(W2[c0 * 2] * a20, W2[c1 * 2] * a20,
                               W2[c0 * 2 + 1] * a21, W2[c1 * 2 + 1] * a21);
        if (tid == 0)
            beta2s = make_float2((b2[0] - m2[0]) * a20 + be2[0],
                                 (b2[1] - m2[1]) * a21 + be2[1]);
    }
    // ---- stage packed adjacency values ----
    if (tid < NJ * 6) {
        int jj = tid / 6, ii = tid % 6;
        float a = (ii < c_cnt[jj]) ? adj[jj * NJ + c_nbr[tid]] : 0.f;
        adjp[tid] = pk2(a, a);
    }
    __syncthreads();

    // ---- Y = (A@X)[j] for SPT samples, splat halves ----
    ull y0d[SPT], y1d[SPT];
    #pragma unroll
    for (int k = 0; k < SPT; ++k) {
        const float* xr = xs + (sl + 32 * k) * HDIM;
        ull y = 0ULL;
        #pragma unroll
        for (int i = 0; i < 6; ++i)
            y = ffma2(adjp[j * 6 + i], *(const ull*)(xr + 2 * c_nbr[j * 6 + i]), y);
        float y0, y1; upk2(y, y0, y1);
        y0d[k] = pk2(y0, y0);
        y1d[k] = pk2(y1, y1);
    }

    // ---- fused layer1 (+BN+relu) -> layer2 channel contraction ----
    ull acc0[SPT], acc1[SPT];
    #pragma unroll
    for (int k = 0; k < SPT; ++k) { acc0[k] = 0ULL; acc1[k] = 0ULL; }
    #pragma unroll
    for (int cp = 0; cp < 32; ++cp) {
        float4 wa = cka[cp];
        float2 bp = ckc[cp];
        float4 wb = ckb[cp];
        ull wa01 = pk2(wa.x, wa.y), wa23 = pk2(wa.z, wa.w);
        ull bpp  = pk2(bp.x, bp.y);
        ull wb01 = pk2(wb.x, wb.y), wb23 = pk2(wb.z, wb.w);
        #pragma unroll
        for (int k = 0; k < SPT; ++k) {
            ull h = ffma2(y0d[k], wa01, ffma2(y1d[k], wa23, bpp));
            float hl, hh; upk2(h, hl, hh);
            h = pk2(fmaxf(hl, 0.f), fmaxf(hh, 0.f));
            acc0[k] = ffma2(h, wb01, acc0[k]);
            acc1[k] = ffma2(h, wb23, acc1[k]);
        }
    }
    #pragma unroll
    for (int k = 0; k < SPT; ++k) {
        float a, b, c, d;
        upk2(acc0[k], a, b);
        upk2(acc1[k], c, d);
        *(float2*)(s2s + (sl + 32 * k) * HDIM + 2 * j) = make_float2(a + b, c + d);
    }
    __syncthreads();   // S2 complete (xs untouched)

    // ---- out = A @ S2 + beta2' + x, direct STG.64 (L2 merges lines) ----
    const float2 b2p = beta2s;
    #pragma unroll
    for (int k = 0; k < SPT; ++k) {
        const int row = (sl + 32 * k) * HDIM;
        const float* sr = s2s + row;
        ull o = pk2(b2p.x, b2p.y);
        #pragma unroll
        for (int i = 0; i < 6; ++i)
            o = ffma2(adjp[j * 6 + i], *(const ull*)(sr + 2 * c_nbr[j * 6 + i]), o);
        o = fadd2(o, *(const ull*)(xs + row + 2 * j));
        long long g = base + row + 2 * j;
        if (g < total) {
            float o0, o1; upk2(o, o0, o1);
            *(float2*)(out + g) = make_float2(o0, o1);
        }
    }
}

extern "C" void kernel_launch(void* const* d_in, const int* in_sizes, int n_in,
                              void* d_out, int out_size) {
    int nsamples = in_sizes[0] / HDIM;
    int grid = (nsamples + SPB - 1) / SPB;
    hand_gcn_kernel<<<grid, NTHREADS>>>(
        (const float*)d_in[0],  (const float*)d_in[1],  (const float*)d_in[2],
        (const float*)d_in[3],  (const float*)d_in[4],  (const float*)d_in[5],
        (const float*)d_in[6],  (const float*)d_in[7],  (const float*)d_in[8],
        (const float*)d_in[9],  (const float*)d_in[10], (const float*)d_in[11],
        (const float*)d_in[12], (const float*)d_in[13],
        (float*)d_out, nsamples);
}

// round 6
// speedup vs baseline: 1.1943x; 1.1943x over previous
#include <cuda_runtime.h>

// HandGraphConvNet fused: 2-layer GCN + BN(eval) + relu + residual, fp32.
//   Y  = A @ X            (sparse A: <=6 nnz/row, fixed hand-skeleton pattern)
//   H  = relu(Y @ W1' + beta1')      (never materialized)
//   S2 = H @ W2'
//   out = A @ S2 + beta2' + x
// Mapping: block = 7 warps x 32 lanes; warp w <-> joints {3w,3w+1,3w+2},
// lane <-> sample, 2 samples/thread => 6 (sample,joint) units share each
// channel-constant load. Constants pre-packed in shared as u64 pairs so the
// hot loop has zero packing MOVs: 3 LDS + 24 ffma2 + 12 fmnmx per iter.

#define NJ 21
#define HDIM 42
#define HIDDEN 64
#define SPB 64                 // samples per block (2 per lane)
#define NTHREADS 224           // 7 warps
#define BN_EPS 1e-5f

typedef unsigned long long ull;

__constant__ int c_nbr[NJ * 6] = {
    0,1,5,9,13,17,
    0,1,2,0,0,0, 1,2,3,0,0,0, 2,3,4,0,0,0, 3,4,0,0,0,0,
    0,5,6,0,0,0, 5,6,7,0,0,0, 6,7,8,0,0,0, 7,8,0,0,0,0,
    0,9,10,0,0,0, 9,10,11,0,0,0, 10,11,12,0,0,0, 11,12,0,0,0,0,
    0,13,14,0,0,0, 13,14,15,0,0,0, 14,15,16,0,0,0, 15,16,0,0,0,0,
    0,17,18,0,0,0, 17,18,19,0,0,0, 18,19,20,0,0,0, 19,20,0,0,0,0};
__constant__ int c_cnt[NJ] = {6,3,3,3,2,3,3,3,2,3,3,3,2,3,3,3,2,3,3,3,2};

__device__ __forceinline__ ull pk2(float lo, float hi) {
    ull r; asm("mov.b64 %0, {%1, %2};" : "=l"(r) : "f"(lo), "f"(hi)); return r;
}
__device__ __forceinline__ void upk2(ull v, float& lo, float& hi) {
    asm("mov.b64 {%0, %1}, %2;" : "=f"(lo), "=f"(hi) : "l"(v));
}
__device__ __forceinline__ ull ffma2(ull a, ull b, ull c) {
    ull d; asm("fma.rn.f32x2 %0, %1, %2, %3;" : "=l"(d) : "l"(a), "l"(b), "l"(c)); return d;
}
__device__ __forceinline__ ull fadd2(ull a, ull b) {
    ull d; asm("add.rn.f32x2 %0, %1, %2;" : "=l"(d) : "l"(a), "l"(b)); return d;
}

__global__ __launch_bounds__(NTHREADS, 3)
void hand_gcn_kernel(const float* __restrict__ x,  const float* __restrict__ adj,
                     const float* __restrict__ W1, const float* __restrict__ b1,
                     const float* __restrict__ W2, const float* __restrict__ b2,
                     const float* __restrict__ g1, const float* __restrict__ be1,
                     const float* __restrict__ m1, const float* __restrict__ v1,
                     const float* __restrict__ g2, const float* __restrict__ be2,
                     const float* __restrict__ m2, const float* __restrict__ v2,
                     float* __restrict__ out, int nsamples)
{
    // lane word-stride 42 mod 32 = 10 -> 64-bit accesses conflict-free
    __shared__ alignas(16) float xs [SPB * HDIM];   // staged X (kept intact)
    __shared__ alignas(16) float s2s[SPB * HDIM];   // S2 scratch
    __shared__ alignas(16) ulonglong2 cap[32];  // packed (W1'col pair lo, hi)
    __shared__ alignas(16) ulonglong2 cbp[32];  // packed (W2'row pair lo, hi)
    __shared__ ull ccp[32];                     // packed beta1' pair
    __shared__ ull adjp[NJ * 6];                // packed (a,a)
    __shared__ ull beta2p;

    const int tid  = threadIdx.x;
    const int w    = tid >> 5;          // warp -> joint triple
    const int lane = tid & 31;          // sample slot
    const long long base  = (long long)blockIdx.x * (SPB * HDIM);
    const long long total = (long long)nsamples * HDIM;

    // ---- stage X: 672 float4 = exactly 3 per thread ----
    float4* xs4 = (float4*)xs;
    #pragma unroll
    for (int i = tid; i < SPB * HDIM / 4; i += NTHREADS) {
        long long g = base + 4LL * i;
        float4 v = make_float4(0.f, 0.f, 0.f, 0.f);
        if (g < total) v = *(const float4*)(x + g);
        xs4[i] = v;
    }

    // ---- fold BN into pre-packed weight/bias constants ----
    if (tid < 32) {
        int c0 = 2 * tid, c1 = c0 + 1;
        float al0 = g1[c0] * rsqrtf(v1[c0] + BN_EPS);
        float al1 = g1[c1] * rsqrtf(v1[c1] + BN_EPS);
        cap[tid] = make_ulonglong2(pk2(W1[c0] * al0, W1[c1] * al1),
                                   pk2(W1[HIDDEN + c0] * al0, W1[HIDDEN + c1] * al1));
        ccp[tid] = pk2((b1[c0] - m1[c0]) * al0 + be1[c0],
                       (b1[c1] - m1[c1]) * al1 + be1[c1]);
        float a20 = g2[0] * rsqrtf(v2[0] + BN_EPS);
        float a21 = g2[1] * rsqrtf(v2[1] + BN_EPS);
        cbp[tid] = make_ulonglong2(pk2(W2[c0 * 2] * a20, W2[c1 * 2] * a20),
                                   pk2(W2[c0 * 2 + 1] * a21, W2[c1 * 2 + 1] * a21));
        if (tid == 0)
            beta2p = pk2((b2[0] - m2[0]) * a20 + be2[0],
                         (b2[1] - m2[1]) * a21 + be2[1]);
    }
    if (tid < NJ * 6) {
        int jj = tid / 6, ii = tid % 6;
        float a = (ii < c_cnt[jj]) ? adj[jj * NJ + c_nbr[tid]] : 0.f;
        adjp[tid] = pk2(a, a);
    }
    __syncthreads();

    // ---- Y = (A@X)[j] for 2 samples x 3 joints, splat halves ----
    ull y0d[6], y1d[6];
    #pragma unroll
    for (int k = 0; k < 2; ++k) {
        const float* xr = xs + (lane + 32 * k) * HDIM;
        #pragma unroll
        for (int jj = 0; jj < 3; ++jj) {
            const int j = 3 * w + jj;
            ull y = 0ULL;
            #pragma unroll
            for (int i = 0; i < 6; ++i)
                y = ffma2(adjp[j * 6 + i], *(const ull*)(xr + 2 * c_nbr[j * 6 + i]), y);
            float y0, y1; upk2(y, y0, y1);
            y0d[k * 3 + jj] = pk2(y0, y0);
            y1d[k * 3 + jj] = pk2(y1, y1);
        }
    }

    // ---- fused layer1 (+BN+relu) -> layer2 contraction, 6 units/thread ----
    ull a0[6], a1[6];
    #pragma unroll
    for (int t = 0; t < 6; ++t) { a0[t] = 0ULL; a1[t] = 0ULL; }
    #pragma unroll
    for (int cp = 0; cp < 32; ++cp) {
        ulonglong2 wa = cap[cp];      // LDS.128 -> packed pair, no MOVs
        ull        bp = ccp[cp];      // LDS.64
        ulonglong2 wb = cbp[cp];      // LDS.128
        #pragma unroll
        for (int t = 0; t < 6; ++t) {
            ull h = ffma2(y0d[t], wa.x, ffma2(y1d[t], wa.y, bp));
            float hl, hh; upk2(h, hl, hh);
            h = pk2(fmaxf(hl, 0.f), fmaxf(hh, 0.f));
            a0[t] = ffma2(h, wb.x, a0[t]);
            a1[t] = ffma2(h, wb.y, a1[t]);
        }
    }
    #pragma unroll
    for (int k = 0; k < 2; ++k)
        #pragma unroll
        for (int jj = 0; jj < 3; ++jj) {
            const int t = k * 3 + jj;
            float p, q, r, s;
            upk2(a0[t], p, q);
            upk2(a1[t], r, s);
            *(float2*)(s2s + (lane + 32 * k) * HDIM + 2 * (3 * w + jj)) =
                make_float2(p + q, r + s);
        }
    __syncthreads();   // S2 complete (xs untouched)

    // ---- out = A @ S2 + beta2' + x, direct scattered STG.64 ----
    const ull b2pk = beta2p;
    #pragma unroll
    for (int k = 0; k < 2; ++k) {
        const int row = (lane + 32 * k) * HDIM;
        const float* sr = s2s + row;
        #pragma unroll
        for (int jj = 0; jj < 3; ++jj) {
            const int j = 3 * w + jj;
            ull o = b2pk;
            #pragma unroll
            for (int i = 0; i < 6; ++i)
                o = ffma2(adjp[j * 6 + i], *(const ull*)(sr + 2 * c_nbr[j * 6 + i]), o);
            o = fadd2(o, *(const ull*)(xs + row + 2 * j));
            long long g = base + row + 2 * j;
            if (g < total) {
                float o0, o1; upk2(o, o0, o1);
                *(float2*)(out + g) = make_float2(o0, o1);
            }
        }
    }
}

extern "C" void kernel_launch(void* const* d_in, const int* in_sizes, int n_in,
                              void* d_out, int out_size) {
    int nsamples = in_sizes[0] / HDIM;
    int grid = (nsamples + SPB - 1) / SPB;
    hand_gcn_kernel<<<grid, NTHREADS>>>(
        (const float*)d_in[0],  (const float*)d_in[1],  (const float*)d_in[2],
        (const float*)d_in[3],  (const float*)d_in[4],  (const float*)d_in[5],
        (const float*)d_in[6],  (const float*)d_in[7],  (const float*)d_in[8],
        (const float*)d_in[9],  (const float*)d_in[10], (const float*)d_in[11],
        (const float*)d_in[12], (const float*)d_in[13],
        (float*)d_out, nsamples);
}